// round 12
// baseline (speedup 1.0000x reference)
#include <cuda_runtime.h>
#include <cuda_bf16.h>
#include <cstdint>

// Problem constants
#define C_IN   8
#define C_OUT  16
#define N_IN   8192      // C_IN*32*32
#define N_OUT  16384     // C_OUT*32*32
#define ROWS   8193      // N_IN + 1
#define COLS   16385     // N_OUT + 1

#define LOHI_BLOCKS 64
#define NTHREADS    256
// Grid: blocks [0, ROWS) = M rows (store stream starts at t=0),
//       blocks [ROWS, ROWS+64) = lo/hi compute (overlaps the store drain).
#define GRID_TOTAL  (ROWS + LOHI_BLOCKS)

__global__ __launch_bounds__(NTHREADS, 8)   // pin <=32 regs -> 8 blocks/SM
void conv_abs_kernel(const float* __restrict__ cl,     // concrete_lower, 8192
                     const float* __restrict__ cu,     // concrete_upper, 8192
                     const float* __restrict__ wgt,    // weights, 16*8*3*3 = 1152
                     const float* __restrict__ bias,   // 16
                     float* __restrict__ out)          // lo[16384] | hi[16384] | M[8193*16385]
{
    const int t = threadIdx.x;

    if (blockIdx.x >= ROWS) {
        // ---- lo/hi path (end of grid): one thread per output pixel ----
        __shared__ float s_w[72];
        int gid = (blockIdx.x - ROWS) * NTHREADS + t;
        int c   = gid >> 10;
        int rem = gid & 1023;
        int i   = rem >> 5;
        int j   = rem & 31;
        if (t < 72) s_w[t] = wgt[c * 72 + t];   // block spans exactly one channel c
        __syncthreads();

        float accL = bias[c];
        float accH = accL;
        #pragma unroll
        for (int ci = 0; ci < C_IN; ci++) {
            #pragma unroll
            for (int kh = 0; kh < 3; kh++) {
                int y = i - 1 + kh;
                if ((unsigned)y >= 32u) continue;
                #pragma unroll
                for (int kw = 0; kw < 3; kw++) {
                    int x = j - 1 + kw;
                    if ((unsigned)x >= 32u) continue;
                    float w   = s_w[(ci * 3 + kh) * 3 + kw];
                    int   tap = ci * 1024 + y * 32 + x;
                    float l = __ldg(cl + tap);
                    float u = __ldg(cu + tap);
                    accL += w * (w > 0.f ? l : u);
                    accH += w * (w > 0.f ? u : l);
                }
            }
        }
        out[gid]         = accL;   // lo
        out[N_OUT + gid] = accH;   // hi
        return;
    }

    // ---- M fill: one block per row, two-phase (zero-stream, then L2-hot patch) ----
    float* __restrict__ M = out + 2 * N_OUT;

    const unsigned r = blockIdx.x;                      // 0..8192
    float* __restrict__ row = M + (size_t)r * (size_t)COLS;

    const float4 z4 = make_float4(0.f, 0.f, 0.f, 0.f);

    if (r < 8192u) {
        // Phase 1: stream zeros over the whole row (65540 B), 16B-aligned body.
        const unsigned p     = (4u - (r & 3u)) & 3u;    // peel to 16B alignment
        const unsigned quads = (16384u - p) >> 2;       // 4096 (p=0) or 4095
        if (t < (int)p) row[t] = 0.f;
        float* __restrict__ ali = row + p;
        #pragma unroll 4
        for (unsigned q = t; q < quads; q += NTHREADS)
            *reinterpret_cast<float4*>(ali + 4u * q) = z4;
        const unsigned tail_start = p + 4u * quads;
        const unsigned ntail = (unsigned)COLS - tail_start;  // 1..4 (covers last col)
        if (t < (int)ntail) row[tail_start + t] = 0.f;

        __syncthreads();  // order phase-1 stores before phase-2 overwrites

        // Phase 2: patch the <=144 nonzeros of this row (L2-resident). r = (ci,y,x).
        if (t < 144) {
            const unsigned ci  = r >> 10;
            const unsigned y   = (r >> 5) & 31u;
            const unsigned x   = r & 31u;
            const unsigned c   = (unsigned)t / 9u;
            const unsigned rem = (unsigned)t - c * 9u;
            const unsigned dy  = rem / 3u;
            const unsigned dx  = rem - dy * 3u;
            const int i = (int)y - 1 + (int)dy;
            const int j = (int)x - 1 + (int)dx;
            if ((unsigned)i < 32u && (unsigned)j < 32u) {
                const unsigned kh  = 2u - dy;
                const unsigned kw  = 2u - dx;
                const unsigned col = c * 1024u + (unsigned)i * 32u + (unsigned)j;
                row[col] = __ldg(wgt + ((c * 8u + ci) * 3u + kh) * 3u + kw);
            }
        }
    } else {
        // Bias row r == 8192 (base 16B-aligned: 8192*16385 % 4 == 0).
        #pragma unroll 4
        for (unsigned q = t; q < 4096u; q += NTHREADS) {
            const unsigned col = 4u * q;
            const float b = __ldg(bias + (col >> 10));
            *reinterpret_cast<float4*>(row + col) = make_float4(b, b, b, b);
        }
        if (t == 0) row[16384] = 1.0f;
    }
}

extern "C" void kernel_launch(void* const* d_in, const int* in_sizes, int n_in,
                              void* d_out, int out_size) {
    const float* cl   = (const float*)d_in[0];
    const float* cu   = (const float*)d_in[1];
    const float* wgt  = (const float*)d_in[2];
    const float* bias = (const float*)d_in[3];
    float* out = (float*)d_out;

    conv_abs_kernel<<<GRID_TOTAL, NTHREADS>>>(cl, cu, wgt, bias, out);
}

// round 13
// speedup vs baseline: 1.0445x; 1.0445x over previous
#include <cuda_runtime.h>
#include <cuda_bf16.h>
#include <cstdint>

// Problem constants
#define C_IN   8
#define C_OUT  16
#define N_IN   8192      // C_IN*32*32
#define N_OUT  16384     // C_OUT*32*32
#define ROWS   8193      // N_IN + 1
#define COLS   16385     // N_OUT + 1

#define LOHI_BLOCKS 64
#define NTHREADS    256

__global__ __launch_bounds__(NTHREADS, 8)   // pin <=32 regs -> 8 blocks/SM
void conv_abs_kernel(const float* __restrict__ cl,     // concrete_lower, 8192
                     const float* __restrict__ cu,     // concrete_upper, 8192
                     const float* __restrict__ wgt,    // weights, 16*8*3*3 = 1152
                     const float* __restrict__ bias,   // 16
                     float* __restrict__ out)          // lo[16384] | hi[16384] | M[8193*16385]
{
    const int t = threadIdx.x;

    if (blockIdx.x < LOHI_BLOCKS) {
        // ---- lo/hi path (start of grid: latency hidden in the store ramp) ----
        __shared__ float s_w[72];
        int gid = blockIdx.x * NTHREADS + t;
        int c   = gid >> 10;
        int rem = gid & 1023;
        int i   = rem >> 5;
        int j   = rem & 31;
        if (t < 72) s_w[t] = wgt[c * 72 + t];   // block spans exactly one channel c
        __syncthreads();

        float accL = bias[c];
        float accH = accL;
        #pragma unroll
        for (int ci = 0; ci < C_IN; ci++) {
            #pragma unroll
            for (int kh = 0; kh < 3; kh++) {
                int y = i - 1 + kh;
                if ((unsigned)y >= 32u) continue;
                #pragma unroll
                for (int kw = 0; kw < 3; kw++) {
                    int x = j - 1 + kw;
                    if ((unsigned)x >= 32u) continue;
                    float w   = s_w[(ci * 3 + kh) * 3 + kw];
                    int   tap = ci * 1024 + y * 32 + x;
                    float l = __ldg(cl + tap);
                    float u = __ldg(cu + tap);
                    accL += w * (w > 0.f ? l : u);
                    accH += w * (w > 0.f ? u : l);
                }
            }
        }
        out[gid]         = accL;   // lo
        out[N_OUT + gid] = accH;   // hi
        return;
    }

    // ---- M fill: one block per row, two-phase (zero-stream, then L2-hot patch) ----
    float* __restrict__ M = out + 2 * N_OUT;

    const unsigned r = blockIdx.x - LOHI_BLOCKS;        // 0..8192
    float* __restrict__ row = M + (size_t)r * (size_t)COLS;

    const float4 z4 = make_float4(0.f, 0.f, 0.f, 0.f);

    if (r < 8192u) {
        // Phase 1: stream zeros over the whole row (65540 B), 16B-aligned body.
        const unsigned p     = (4u - (r & 3u)) & 3u;    // peel to 16B alignment
        const unsigned quads = (16384u - p) >> 2;       // 4096 (p=0) or 4095
        if (t < (int)p) row[t] = 0.f;
        float* __restrict__ ali = row + p;
        #pragma unroll 4
        for (unsigned q = t; q < quads; q += NTHREADS)
            *reinterpret_cast<float4*>(ali + 4u * q) = z4;
        const unsigned tail_start = p + 4u * quads;
        const unsigned ntail = (unsigned)COLS - tail_start;  // 1..4 (covers last col)
        if (t < (int)ntail) row[tail_start + t] = 0.f;

        __syncthreads();  // order phase-1 stores before phase-2 overwrites

        // Phase 2: patch the <=144 nonzeros of this row (L2-resident). r = (ci,y,x).
        if (t < 144) {
            const unsigned ci  = r >> 10;
            const unsigned y   = (r >> 5) & 31u;
            const unsigned x   = r & 31u;
            const unsigned c   = (unsigned)t / 9u;
            const unsigned rem = (unsigned)t - c * 9u;
            const unsigned dy  = rem / 3u;
            const unsigned dx  = rem - dy * 3u;
            const int i = (int)y - 1 + (int)dy;
            const int j = (int)x - 1 + (int)dx;
            if ((unsigned)i < 32u && (unsigned)j < 32u) {
                const unsigned kh  = 2u - dy;
                const unsigned kw  = 2u - dx;
                const unsigned col = c * 1024u + (unsigned)i * 32u + (unsigned)j;
                row[col] = __ldg(wgt + ((c * 8u + ci) * 3u + kh) * 3u + kw);
            }
        }
    } else {
        // Bias row r == 8192 (base 16B-aligned: 8192*16385 % 4 == 0).
        #pragma unroll 4
        for (unsigned q = t; q < 4096u; q += NTHREADS) {
            const unsigned col = 4u * q;
            const float b = __ldg(bias + (col >> 10));
            *reinterpret_cast<float4*>(row + col) = make_float4(b, b, b, b);
        }
        if (t == 0) row[16384] = 1.0f;
    }
}

extern "C" void kernel_launch(void* const* d_in, const int* in_sizes, int n_in,
                              void* d_out, int out_size) {
    const float* cl   = (const float*)d_in[0];
    const float* cu   = (const float*)d_in[1];
    const float* wgt  = (const float*)d_in[2];
    const float* bias = (const float*)d_in[3];
    float* out = (float*)d_out;

    conv_abs_kernel<<<LOHI_BLOCKS + ROWS, NTHREADS>>>(cl, cu, wgt, bias, out);
}

// round 14
// speedup vs baseline: 1.0887x; 1.0423x over previous
#include <cuda_runtime.h>
#include <cuda_bf16.h>
#include <cstdint>

// Problem constants
#define C_IN   8
#define C_OUT  16
#define N_IN   8192      // C_IN*32*32
#define N_OUT  16384     // C_OUT*32*32
#define ROWS   8193      // N_IN + 1
#define COLS   16385     // N_OUT + 1

#define LOHI_BLOCKS 64
#define NTHREADS    256
// Grid: [0,64) lo/hi, block 64 = bias row, [65, 65+2*8192) = half-rows of M.
#define GRID_TOTAL  (LOHI_BLOCKS + 1 + 2 * 8192)

__global__ __launch_bounds__(NTHREADS, 8)   // pin <=32 regs -> 8 blocks/SM
void conv_abs_kernel(const float* __restrict__ cl,     // concrete_lower, 8192
                     const float* __restrict__ cu,     // concrete_upper, 8192
                     const float* __restrict__ wgt,    // weights, 16*8*3*3 = 1152
                     const float* __restrict__ bias,   // 16
                     float* __restrict__ out)          // lo[16384] | hi[16384] | M[8193*16385]
{
    const int t = threadIdx.x;
    float* __restrict__ M = out + 2 * N_OUT;

    if (blockIdx.x < LOHI_BLOCKS) {
        // ---- lo/hi path (start of grid: latency hidden in the store ramp) ----
        __shared__ float s_w[72];
        int gid = blockIdx.x * NTHREADS + t;
        int c   = gid >> 10;
        int rem = gid & 1023;
        int i   = rem >> 5;
        int j   = rem & 31;
        if (t < 72) s_w[t] = wgt[c * 72 + t];   // block spans exactly one channel c
        __syncthreads();

        float accL = bias[c];
        float accH = accL;
        #pragma unroll
        for (int ci = 0; ci < C_IN; ci++) {
            #pragma unroll
            for (int kh = 0; kh < 3; kh++) {
                int y = i - 1 + kh;
                if ((unsigned)y >= 32u) continue;
                #pragma unroll
                for (int kw = 0; kw < 3; kw++) {
                    int x = j - 1 + kw;
                    if ((unsigned)x >= 32u) continue;
                    float w   = s_w[(ci * 3 + kh) * 3 + kw];
                    int   tap = ci * 1024 + y * 32 + x;
                    float l = __ldg(cl + tap);
                    float u = __ldg(cu + tap);
                    accL += w * (w > 0.f ? l : u);
                    accH += w * (w > 0.f ? u : l);
                }
            }
        }
        out[gid]         = accL;   // lo
        out[N_OUT + gid] = accH;   // hi
        return;
    }

    if (blockIdx.x == LOHI_BLOCKS) {
        // ---- bias row r == 8192 (base 16B-aligned: 8192*16385 % 4 == 0) ----
        float* __restrict__ brow = M + (size_t)8192 * (size_t)COLS;
        #pragma unroll 4
        for (unsigned q = t; q < 4096u; q += NTHREADS) {
            const unsigned col = 4u * q;
            const float b = __ldg(bias + (col >> 10));
            *reinterpret_cast<float4*>(brow + col) = make_float4(b, b, b, b);
        }
        if (t == 0) brow[16384] = 1.0f;
        return;
    }

    // ---- M fill: one block per HALF-row, two-phase (zero-stream, then patch) ----
    const unsigned hb   = blockIdx.x - (LOHI_BLOCKS + 1);  // 0..16383
    const unsigned r    = hb >> 1;                          // row 0..8191
    const unsigned half = hb & 1u;                          // 0: cols[0,8192) 1: cols[8192,16385)

    float* __restrict__ row = M + (size_t)r * (size_t)COLS;
    const unsigned cbeg  = half ? 8192u : 0u;
    const unsigned nelem = half ? 8193u : 8192u;            // half 1 includes last col

    // Both halves start at flat offset ≡ r (mod 4): 16385%4==1, 8192%4==0.
    const unsigned p = (4u - (r & 3u)) & 3u;                // peel to 16B alignment
    if (t < (int)p) row[cbeg + t] = 0.f;

    const unsigned quads = (nelem - p) >> 2;                // 2048/2047 or ~2048
    float* __restrict__ ali = row + cbeg + p;
    const float4 z4 = make_float4(0.f, 0.f, 0.f, 0.f);
    #pragma unroll 4
    for (unsigned q = t; q < quads; q += NTHREADS)
        *reinterpret_cast<float4*>(ali + 4u * q) = z4;

    const unsigned tail_start = p + 4u * quads;
    const unsigned ntail = nelem - tail_start;              // 0..3 (incl. last col in half 1)
    if (t < (int)ntail) row[cbeg + tail_start + t] = 0.f;

    __syncthreads();  // order phase-1 stores before phase-2 overwrites

    // Phase 2: patch this half's 72 taps (channels [8*half, 8*half+8)). r = (ci,y,x).
    if (t < 72) {
        const unsigned ci  = r >> 10;
        const unsigned y   = (r >> 5) & 31u;
        const unsigned x   = r & 31u;
        const unsigned c   = 8u * half + (unsigned)t / 9u;
        const unsigned rem = (unsigned)t % 9u;
        const unsigned dy  = rem / 3u;
        const unsigned dx  = rem - dy * 3u;
        const int i = (int)y - 1 + (int)dy;
        const int j = (int)x - 1 + (int)dx;
        if ((unsigned)i < 32u && (unsigned)j < 32u) {
            const unsigned kh  = 2u - dy;
            const unsigned kw  = 2u - dx;
            const unsigned col = c * 1024u + (unsigned)i * 32u + (unsigned)j;  // in this half
            row[col] = __ldg(wgt + ((c * 8u + ci) * 3u + kh) * 3u + kw);
        }
    }
}

extern "C" void kernel_launch(void* const* d_in, const int* in_sizes, int n_in,
                              void* d_out, int out_size) {
    const float* cl   = (const float*)d_in[0];
    const float* cu   = (const float*)d_in[1];
    const float* wgt  = (const float*)d_in[2];
    const float* bias = (const float*)d_in[3];
    float* out = (float*)d_out;

    conv_abs_kernel<<<GRID_TOTAL, NTHREADS>>>(cl, cu, wgt, bias, out);
}